// round 14
// baseline (speedup 1.0000x reference)
#include <cuda_runtime.h>
#include <cuda_fp16.h>
#include <math.h>
#include <stdint.h>

// Problem constants
#define NN 50000
#define EE 800000
#define DD 512
#define BB 64
#define LL 4
#define EPSV 1e-5f

#define SCAN_TPB 256
#define SCAN_NB ((NN + SCAN_TPB - 1) / SCAN_TPB)   // 196

// GEMM config: BM=BN=128, BK=64 halves, 3-stage cp.async, XOR-swizzled smem
#define BKH 64
#define ROWB 128
#define STG_BYTES (128 * ROWB)      // 16384
#define STAGE_BYTES (2 * STG_BYTES) // 32768
#define NSTAGE 3
#define GSMEM_BYTES (NSTAGE * STAGE_BYTES)   // 98304 -> 2 CTAs/SM

#define PSLICE 8

// ---------------- device scratch (allocation-free) ----------------
__device__ unsigned long long g_pk[NN];   // packed (count_sd1 << 32) | count_sd0
__device__ float g_dis[NN];
__device__ int   g_cnt[NN];
__device__ int   g_off[NN + 1];
__device__ int   g_bsum[SCAN_NB];
__device__ __align__(16) int2 g_edge[EE]; // interleaved (src, norm-bits)
__device__ __align__(16) __half g_x16[(size_t)NN * DD];
__device__ __align__(16) __half g_wt[(size_t)LL * DD * DD]; // W^T * BNscale fp16 [l][n][k]
__device__ float g_cbias[LL * DD];
__device__ __align__(16) __half g_hw16[(size_t)NN * DD];
__device__ __align__(16) __half g_h16[(size_t)NN * DD];
__device__ int   g_gcnt[BB];
__device__ int   g_gstart[BB + 1];
__device__ float g_psum[PSLICE][BB][DD];
__device__ float g_pmax[PSLICE][BB][DD];
__device__ float g_pool[BB * 2 * DD];

// ---------------- init ----------------
__global__ void init_kernel() {
    int i = blockIdx.x * blockDim.x + threadIdx.x;
    if (i < NN) g_pk[i] = 0ull;
    if (i < BB) g_gcnt[i] = 0;
}

__global__ void edge_deg_kernel(const int* __restrict__ ei,
                                const int* __restrict__ sd) {
    int e = blockIdx.x * blockDim.x + threadIdx.x;
    if (e >= EE) return;
    int col = ei[EE + e];
    unsigned long long inc = (sd[e] == 1) ? (1ull << 32) : 1ull;
    atomicAdd(&g_pk[col], inc);
}

__global__ void finalize_deg_kernel() {
    int i = blockIdx.x * blockDim.x + threadIdx.x;
    if (i >= NN) return;
    unsigned long long pk = g_pk[i];
    unsigned int lo = (unsigned int)(pk & 0xffffffffull);
    unsigned int hi = (unsigned int)(pk >> 32);
    g_cnt[i] = (int)(lo + hi);
    float d = (float)hi + 0.7f * (float)lo + 1.0f;
    g_dis[i] = rsqrtf(fmaxf(d, EPSV));
}

// x -> fp16
__global__ void x2h_kernel(const float* __restrict__ x) {
    size_t i = (size_t)blockIdx.x * blockDim.x + threadIdx.x;
    size_t total = (size_t)NN * DD;
    if (i * 4 < total) {
        float4 v = *(const float4*)(x + i * 4);
        __half2 h0 = __floats2half2_rn(v.x, v.y);
        __half2 h1 = __floats2half2_rn(v.z, v.w);
        *(uint2*)(g_x16 + i * 4) = make_uint2(*(uint32_t*)&h0, *(uint32_t*)&h1);
    }
}

// W[l][k][n] * BNscale[l][n] -> g_wt[l][n][k] fp16
__global__ void wt_kernel(const float* __restrict__ Wc,
                          const float* __restrict__ gamma,
                          const float* __restrict__ rvar) {
    __shared__ float tile[32][33];
    int l = blockIdx.z;
    int n0 = blockIdx.x * 32;
    int k0 = blockIdx.y * 32;
    int tx = threadIdx.x, ty = threadIdx.y;
    tile[ty][tx] = Wc[(size_t)l * DD * DD + (size_t)(k0 + ty) * DD + n0 + tx];
    __syncthreads();
    int n = n0 + ty;
    float scale = gamma[l * DD + n] * rsqrtf(rvar[l * DD + n] + EPSV);
    g_wt[(size_t)l * DD * DD + (size_t)n * DD + k0 + tx] =
        __float2half_rn(tile[tx][ty] * scale);
}

__global__ void cbias_kernel(const float* __restrict__ bc,
                             const float* __restrict__ gamma,
                             const float* __restrict__ beta,
                             const float* __restrict__ rmean,
                             const float* __restrict__ rvar) {
    int i = blockIdx.x * blockDim.x + threadIdx.x;
    if (i >= LL * DD) return;
    float scale = gamma[i] * rsqrtf(rvar[i] + EPSV);
    g_cbias[i] = scale * (bc[i] - rmean[i]) + beta[i];
}

// ---------------- multi-block scan ----------------
__global__ void scan_local_kernel() {
    __shared__ int swarp[8];
    int tid = threadIdx.x;
    int lane = tid & 31, wid = tid >> 5;
    int i = blockIdx.x * SCAN_TPB + tid;
    int v = (i < NN) ? g_cnt[i] : 0;
    int incl = v;
#pragma unroll
    for (int d = 1; d < 32; d <<= 1) {
        int t = __shfl_up_sync(0xffffffff, incl, d);
        if (lane >= d) incl += t;
    }
    if (lane == 31) swarp[wid] = incl;
    __syncthreads();
    if (wid == 0 && lane < 8) {
        int ws = swarp[lane];
        int wincl = ws;
#pragma unroll
        for (int d = 1; d < 8; d <<= 1) {
            int t = __shfl_up_sync(0xff, wincl, d);
            if (lane >= d) wincl += t;
        }
        swarp[lane] = wincl - ws;
        if (lane == 7) g_bsum[blockIdx.x] = wincl;
    }
    __syncthreads();
    if (i < NN) g_off[i] = swarp[wid] + incl - v;
}

__global__ void scan_bsums_kernel() {
    __shared__ int swarp[8];
    int tid = threadIdx.x;
    int lane = tid & 31, wid = tid >> 5;
    int v = (tid < SCAN_NB) ? g_bsum[tid] : 0;
    int incl = v;
#pragma unroll
    for (int d = 1; d < 32; d <<= 1) {
        int t = __shfl_up_sync(0xffffffff, incl, d);
        if (lane >= d) incl += t;
    }
    if (lane == 31) swarp[wid] = incl;
    __syncthreads();
    if (wid == 0 && lane < 8) {
        int ws = swarp[lane];
        int wincl = ws;
#pragma unroll
        for (int d = 1; d < 8; d <<= 1) {
            int t = __shfl_up_sync(0xff, wincl, d);
            if (lane >= d) wincl += t;
        }
        swarp[lane] = wincl - ws;
        if (lane == 7) g_off[NN] = wincl;
    }
    __syncthreads();
    if (tid < SCAN_NB) g_bsum[tid] = swarp[wid] + incl - v;
}

__global__ void scan_add_kernel() {
    int i = blockIdx.x * SCAN_TPB + threadIdx.x;
    if (i < NN) { g_off[i] += g_bsum[blockIdx.x]; g_cnt[i] = 0; }
}

// single 8B scatter per edge
__global__ void bucket_kernel(const int* __restrict__ ei,
                              const int* __restrict__ sd) {
    int e = blockIdx.x * blockDim.x + threadIdx.x;
    if (e >= EE) return;
    int row = ei[e];
    int col = ei[EE + e];
    float w = (sd[e] == 1) ? 1.0f : 0.7f;
    int pos = g_off[col] + atomicAdd(&g_cnt[col], 1);
    float nm = g_dis[row] * w * g_dis[col];
    g_edge[pos] = make_int2(row, __float_as_int(nm));
}

// ============= fp16 mma.sync GEMM, cp.async 3-stage, swizzled =============
__device__ __forceinline__ void mma_f16(float* c, const uint32_t* a, const uint32_t* b) {
    asm volatile(
        "mma.sync.aligned.m16n8k16.row.col.f32.f16.f16.f32 "
        "{%0,%1,%2,%3}, {%4,%5,%6,%7}, {%8,%9}, {%0,%1,%2,%3};\n"
        : "+f"(c[0]), "+f"(c[1]), "+f"(c[2]), "+f"(c[3])
        : "r"(a[0]), "r"(a[1]), "r"(a[2]), "r"(a[3]), "r"(b[0]), "r"(b[1]));
}

__device__ __forceinline__ void ldsm_x4(uint32_t& d0, uint32_t& d1, uint32_t& d2,
                                        uint32_t& d3, uint32_t addr) {
    asm volatile("ldmatrix.sync.aligned.m8n8.x4.shared.b16 {%0,%1,%2,%3}, [%4];"
                 : "=r"(d0), "=r"(d1), "=r"(d2), "=r"(d3) : "r"(addr));
}

__device__ __forceinline__ void cp16(uint32_t dst, const void* src, int srcsize) {
    asm volatile("cp.async.cg.shared.global [%0], [%1], 16, %2;"
                 :: "r"(dst), "l"(src), "r"(srcsize) : "memory");
}

__device__ __forceinline__ uint32_t swz(int row, int ch) {
    return (uint32_t)(row * ROWB + ((ch ^ (row & 7)) << 4));
}

// 256 threads, 8 warps (4M x 2N), warp tile 32x64.
__global__ __launch_bounds__(256)
void gemm_cp_kernel(int use_x, int layer) {
    extern __shared__ char smem[];
    const __half* __restrict__ A = use_x ? g_x16 : g_h16;
    const __half* __restrict__ Bt = g_wt + (size_t)layer * DD * DD;

    int tid = threadIdx.x;
    int lane = tid & 31, warp = tid >> 5;
    int warpM = warp & 3, warpN = warp >> 2;
    int gid = lane >> 2, tig = lane & 3;
    int rowC0 = blockIdx.y * 128;
    int colC0 = blockIdx.x * 128;

    auto load_stage = [&](int kt, int stg) {
        char* sa = smem + stg * STAGE_BYTES;
        char* sb = sa + STG_BYTES;
        uint32_t sa_u = (uint32_t)__cvta_generic_to_shared(sa);
        uint32_t sb_u = (uint32_t)__cvta_generic_to_shared(sb);
#pragma unroll
        for (int i = 0; i < 4; i++) {
            int c = tid + i * 256;
            int row = c >> 3;
            int kc8 = c & 7;
            uint32_t soff = swz(row, kc8);
            int gRow = rowC0 + row;
            const __half* srcA = A + (size_t)gRow * DD + kt * BKH + kc8 * 8;
            cp16(sa_u + soff, srcA, (gRow < NN) ? 16 : 0);
            const __half* srcB = Bt + (size_t)(colC0 + row) * DD + kt * BKH + kc8 * 8;
            cp16(sb_u + soff, srcB, 16);
        }
        asm volatile("cp.async.commit_group;" ::: "memory");
    };

    float acc[2][8][4] = {};

    load_stage(0, 0);
    load_stage(1, 1);

    const int NT = DD / BKH;   // 8
    for (int kt = 0; kt < NT; kt++) {
        if (kt == NT - 1)
            asm volatile("cp.async.wait_group 0;" ::: "memory");
        else
            asm volatile("cp.async.wait_group 1;" ::: "memory");
        __syncthreads();

        if (kt + NSTAGE - 1 < NT)
            load_stage(kt + NSTAGE - 1, (kt + NSTAGE - 1) % NSTAGE);

        int stg = kt % NSTAGE;
        char* sa = smem + stg * STAGE_BYTES;
        char* sb = sa + STG_BYTES;
        uint32_t sa_u = (uint32_t)__cvta_generic_to_shared(sa);
        uint32_t sb_u = (uint32_t)__cvta_generic_to_shared(sb);

#pragma unroll
        for (int ks = 0; ks < BKH / 16; ks++) {
            uint32_t af[2][4];
#pragma unroll
            for (int mt = 0; mt < 2; mt++) {
                int r = warpM * 32 + mt * 16 + (lane & 15);
                int ch = ks * 2 + (lane >> 4);
                ldsm_x4(af[mt][0], af[mt][1], af[mt][2], af[mt][3], sa_u + swz(r, ch));
            }
            uint32_t bf[4][4];
#pragma unroll
            for (int p = 0; p < 4; p++) {
                int n = warpN * 64 + p * 16 + (lane & 7) + ((lane >> 4) * 8);
                int ch = ks * 2 + ((lane >> 3) & 1);
                ldsm_x4(bf[p][0], bf[p][1], bf[p][2], bf[p][3], sb_u + swz(n, ch));
            }
#pragma unroll
            for (int mt = 0; mt < 2; mt++)
#pragma unroll
                for (int nt = 0; nt < 8; nt++)
                    mma_f16(acc[mt][nt], af[mt], &bf[nt >> 1][(nt & 1) * 2]);
        }
    }

    // epilogue: write fp16
#pragma unroll
    for (int mt = 0; mt < 2; mt++) {
        int r0 = rowC0 + warpM * 32 + mt * 16 + gid;
        int r1 = r0 + 8;
#pragma unroll
        for (int nt = 0; nt < 8; nt++) {
            int c = colC0 + warpN * 64 + nt * 8 + tig * 2;
            if (r0 < NN)
                *(__half2*)(g_hw16 + (size_t)r0 * DD + c) =
                    __floats2half2_rn(acc[mt][nt][0], acc[mt][nt][1]);
            if (r1 < NN)
                *(__half2*)(g_hw16 + (size_t)r1 * DD + c) =
                    __floats2half2_rn(acc[mt][nt][2], acc[mt][nt][3]);
        }
    }
}

// ------- aggregation + folded bias + ReLU (4-deep unroll, int2 edges) -------
__global__ __launch_bounds__(64)
void agg_kernel(int layer) {
    int node = blockIdx.x;
    int t = threadIdx.x;               // channels [8t, 8t+7]
    const uint4* hw = (const uint4*)g_hw16;
    int s = g_off[node], e = g_off[node + 1];

    float dn = g_dis[node];
    float sn = dn * dn;

    float acc[8];
    {
        uint4 v = hw[(size_t)node * 64 + t];
        float2 f0 = __half22float2(*(const __half2*)&v.x);
        float2 f1 = __half22float2(*(const __half2*)&v.y);
        float2 f2 = __half22float2(*(const __half2*)&v.z);
        float2 f3 = __half22float2(*(const __half2*)&v.w);
        acc[0] = sn * f0.x; acc[1] = sn * f0.y; acc[2] = sn * f1.x; acc[3] = sn * f1.y;
        acc[4] = sn * f2.x; acc[5] = sn * f2.y; acc[6] = sn * f3.x; acc[7] = sn * f3.y;
    }

    int j = s;
    for (; j + 4 <= e; j += 4) {
        int2 e0 = g_edge[j],     e1 = g_edge[j + 1];
        int2 e2 = g_edge[j + 2], e3 = g_edge[j + 3];
        float n0 = __int_as_float(e0.y), n1 = __int_as_float(e1.y);
        float n2 = __int_as_float(e2.y), n3 = __int_as_float(e3.y);
        uint4 v0 = hw[(size_t)e0.x * 64 + t];
        uint4 v1 = hw[(size_t)e1.x * 64 + t];
        uint4 v2 = hw[(size_t)e2.x * 64 + t];
        uint4 v3 = hw[(size_t)e3.x * 64 + t];
        {
            float2 a0 = __half22float2(*(const __half2*)&v0.x);
            float2 a1 = __half22float2(*(const __half2*)&v0.y);
            float2 a2 = __half22float2(*(const __half2*)&v0.z);
            float2 a3 = __half22float2(*(const __half2*)&v0.w);
            acc[0] += n0 * a0.x; acc[1] += n0 * a0.y; acc[2] += n0 * a1.x; acc[3] += n0 * a1.y;
            acc[4] += n0 * a2.x; acc[5] += n0 * a2.y; acc[6] += n0 * a3.x; acc[7] += n0 * a3.y;
        }
        {
            float2 a0 = __half22float2(*(const __half2*)&v1.x);
            float2 a1 = __half22float2(*(const __half2*)&v1.y);
            float2 a2 = __half22float2(*(const __half2*)&v1.z);
            float2 a3 = __half22float2(*(const __half2*)&v1.w);
            acc[0] += n1 * a0.x; acc[1] += n1 * a0.y; acc[2] += n1 * a1.x; acc[3] += n1 * a1.y;
            acc[4] += n1 * a2.x; acc[5] += n1 * a2.y; acc[6] += n1 * a3.x; acc[7] += n1 * a3.y;
        }
        {
            float2 a0 = __half22float2(*(const __half2*)&v2.x);
            float2 a1 = __half22float2(*(const __half2*)&v2.y);
            float2 a2 = __half22float2(*(const __half2*)&v2.z);
            float2 a3 = __half22float2(*(const __half2*)&v2.w);
            acc[0] += n2 * a0.x; acc[1] += n2 * a0.y; acc[2] += n2 * a1.x; acc[3] += n2 * a1.y;
            acc[4] += n2 * a2.x; acc[5] += n2 * a2.y; acc[6] += n2 * a3.x; acc[7] += n2 * a3.y;
        }
        {
            float2 a0 = __half22float2(*(const __half2*)&v3.x);
            float2 a1 = __half22float2(*(const __half2*)&v3.y);
            float2 a2 = __half22float2(*(const __half2*)&v3.z);
            float2 a3 = __half22float2(*(const __half2*)&v3.w);
            acc[0] += n3 * a0.x; acc[1] += n3 * a0.y; acc[2] += n3 * a1.x; acc[3] += n3 * a1.y;
            acc[4] += n3 * a2.x; acc[5] += n3 * a2.y; acc[6] += n3 * a3.x; acc[7] += n3 * a3.y;
        }
    }
    for (; j < e; j++) {
        int2 ed = g_edge[j];
        float nw = __int_as_float(ed.y);
        uint4 v = hw[(size_t)ed.x * 64 + t];
        float2 f0 = __half22float2(*(const __half2*)&v.x);
        float2 f1 = __half22float2(*(const __half2*)&v.y);
        float2 f2 = __half22float2(*(const __half2*)&v.z);
        float2 f3 = __half22float2(*(const __half2*)&v.w);
        acc[0] += nw * f0.x; acc[1] += nw * f0.y; acc[2] += nw * f1.x; acc[3] += nw * f1.y;
        acc[4] += nw * f2.x; acc[5] += nw * f2.y; acc[6] += nw * f3.x; acc[7] += nw * f3.y;
    }

    float4 cb0 = ((const float4*)g_cbias)[layer * 128 + 2 * t];
    float4 cb1 = ((const float4*)g_cbias)[layer * 128 + 2 * t + 1];
    float o0 = fmaxf(acc[0] + cb0.x, 0.f);
    float o1 = fmaxf(acc[1] + cb0.y, 0.f);
    float o2 = fmaxf(acc[2] + cb0.z, 0.f);
    float o3 = fmaxf(acc[3] + cb0.w, 0.f);
    float o4 = fmaxf(acc[4] + cb1.x, 0.f);
    float o5 = fmaxf(acc[5] + cb1.y, 0.f);
    float o6 = fmaxf(acc[6] + cb1.z, 0.f);
    float o7 = fmaxf(acc[7] + cb1.w, 0.f);
    __half2 h0 = __floats2half2_rn(o0, o1);
    __half2 h1 = __floats2half2_rn(o2, o3);
    __half2 h2 = __floats2half2_rn(o4, o5);
    __half2 h3 = __floats2half2_rn(o6, o7);
    ((uint4*)g_h16)[(size_t)node * 64 + t] =
        make_uint4(*(uint32_t*)&h0, *(uint32_t*)&h1, *(uint32_t*)&h2, *(uint32_t*)&h3);
}

// ---------------- pooling (sliced) ----------------
__global__ void batch_count_kernel(const int* __restrict__ batch) {
    int i = blockIdx.x * blockDim.x + threadIdx.x;
    if (i < NN) atomicAdd(&g_gcnt[batch[i]], 1);
}

__global__ void gscan_kernel() {
    if (threadIdx.x == 0) {
        int run = 0;
        for (int b = 0; b < BB; b++) { g_gstart[b] = run; run += g_gcnt[b]; }
        g_gstart[BB] = run;
    }
}

__global__ void pool_part_kernel() {
    int b = blockIdx.x;
    int c = blockIdx.y * 128 + threadIdx.x;
    int si = blockIdx.z;
    int gs = g_gstart[b], ge = g_gstart[b + 1];
    int len = ge - gs;
    int s = gs + (int)((long long)len * si / PSLICE);
    int e = gs + (int)((long long)len * (si + 1) / PSLICE);
    float sum0 = 0.f, sum1 = 0.f, sum2 = 0.f, sum3 = 0.f;
    float mx0 = -3.0e38f, mx1 = -3.0e38f, mx2 = -3.0e38f, mx3 = -3.0e38f;
    int n = s;
    for (; n + 4 <= e; n += 4) {
        float v0 = __half2float(g_h16[(size_t)n * DD + c]);
        float v1 = __half2float(g_h16[(size_t)(n + 1) * DD + c]);
        float v2 = __half2float(g_h16[(size_t)(n + 2) * DD + c]);
        float v3 = __half2float(g_h16[(size_t)(n + 3) * DD + c]);
        sum0 += v0; sum1 += v1; sum2 += v2; sum3 += v3;
        mx0 = fmaxf(mx0, v0); mx1 = fmaxf(mx1, v1);
        mx2 = fmaxf(mx2, v2); mx3 = fmaxf(mx3, v3);
    }
    for (; n < e; n++) {
        float v = __half2float(g_h16[(size_t)n * DD + c]);
        sum0 += v; mx0 = fmaxf(mx0, v);
    }
    g_psum[si][b][c] = (sum0 + sum1) + (sum2 + sum3);
    g_pmax[si][b][c] = fmaxf(fmaxf(mx0, mx1), fmaxf(mx2, mx3));
}

__global__ void pool_combine_kernel() {
    int b = blockIdx.x;
    int c = blockIdx.y * 128 + threadIdx.x;
    float sum = 0.f, mx = -3.0e38f;
#pragma unroll
    for (int si = 0; si < PSLICE; si++) {
        sum += g_psum[si][b][c];
        mx = fmaxf(mx, g_pmax[si][b][c]);
    }
    int cnt = g_gstart[b + 1] - g_gstart[b];
    float mean = sum / fmaxf((float)cnt, 1.0f);
    if (cnt == 0) mx = 0.f;
    g_pool[b * 2 * DD + c] = mean;
    g_pool[b * 2 * DD + DD + c] = mx;
}

// ---------------- head ----------------
__global__ void final_kernel(const float* __restrict__ Wlin,
                             const float* __restrict__ blin,
                             float* __restrict__ out) {
    int b = blockIdx.x;
    int tid = threadIdx.x;
    const float* p = g_pool + b * 2 * DD;
    float a0 = 0.f, a1 = 0.f;
    for (int j = tid; j < 2 * DD; j += 256) {
        float v = p[j];
        a0 += v * Wlin[2 * j];
        a1 += v * Wlin[2 * j + 1];
    }
    __shared__ float s0[256], s1[256];
    s0[tid] = a0; s1[tid] = a1;
    __syncthreads();
    for (int off = 128; off > 0; off >>= 1) {
        if (tid < off) { s0[tid] += s0[tid + off]; s1[tid] += s1[tid + off]; }
        __syncthreads();
    }
    if (tid == 0) {
        float z0 = s0[0] + blin[0];
        float z1 = s1[0] + blin[1];
        float m = fmaxf(z0, z1);
        float ls = logf(expf(z0 - m) + expf(z1 - m));
        out[b * 2 + 0] = z0 - m - ls;
        out[b * 2 + 1] = z1 - m - ls;
    }
}

// ---------------- launch ----------------
extern "C" void kernel_launch(void* const* d_in, const int* in_sizes, int n_in,
                              void* d_out, int out_size) {
    const float* x     = (const float*)d_in[0];
    const int*   ei    = (const int*)d_in[1];
    const int*   batch = (const int*)d_in[2];
    const int*   sd    = (const int*)d_in[3];
    const float* Wc    = (const float*)d_in[4];
    const float* bc    = (const float*)d_in[5];
    const float* gamma = (const float*)d_in[6];
    const float* beta  = (const float*)d_in[7];
    const float* rmean = (const float*)d_in[8];
    const float* rvar  = (const float*)d_in[9];
    const float* Wlin  = (const float*)d_in[10];
    const float* blin  = (const float*)d_in[11];
    float* out = (float*)d_out;

    cudaFuncSetAttribute(gemm_cp_kernel,
                         cudaFuncAttributeMaxDynamicSharedMemorySize, GSMEM_BYTES);

    const int TPB = 256;
    int gN = (NN + TPB - 1) / TPB;
    int gE = (EE + TPB - 1) / TPB;
    dim3 ggrid(DD / 128, (NN + 127) / 128);

    x2h_kernel<<<(NN * DD / 4 + TPB - 1) / TPB, TPB>>>(x);
    wt_kernel<<<dim3(16, 16, LL), dim3(32, 32)>>>(Wc, gamma, rvar);
    init_kernel<<<gN, TPB>>>();
    gemm_cp_kernel<<<ggrid, 256, GSMEM_BYTES>>>(1, 0);      // 4th launch -> profiled

    edge_deg_kernel<<<gE, TPB>>>(ei, sd);
    finalize_deg_kernel<<<gN, TPB>>>();
    scan_local_kernel<<<SCAN_NB, SCAN_TPB>>>();
    scan_bsums_kernel<<<1, SCAN_TPB>>>();
    scan_add_kernel<<<SCAN_NB, SCAN_TPB>>>();
    bucket_kernel<<<gE, TPB>>>(ei, sd);
    batch_count_kernel<<<gN, TPB>>>(batch);
    gscan_kernel<<<1, 32>>>();
    cbias_kernel<<<(LL * DD + TPB - 1) / TPB, TPB>>>(bc, gamma, beta, rmean, rvar);

    agg_kernel<<<NN, 64>>>(0);
    for (int l = 1; l < LL; l++) {
        gemm_cp_kernel<<<ggrid, 256, GSMEM_BYTES>>>(0, l);
        agg_kernel<<<NN, 64>>>(l);
    }

    pool_part_kernel<<<dim3(BB, DD / 128, PSLICE), 128>>>();
    pool_combine_kernel<<<dim3(BB, DD / 128), 128>>>();
    final_kernel<<<BB, 256>>>(Wlin, blin, out);
}

// round 15
// speedup vs baseline: 1.4229x; 1.4229x over previous
#include <cuda_runtime.h>
#include <cuda_fp16.h>
#include <math.h>
#include <stdint.h>

// Problem constants
#define NN 50000
#define EE 800000
#define DD 512
#define BB 64
#define LL 4
#define EPSV 1e-5f

#define SCAN_TPB 256
#define SCAN_NB ((NN + SCAN_TPB - 1) / SCAN_TPB)   // 196

// GEMM config: BM=BN=128, BK=64 halves, 3-stage cp.async, XOR-swizzled smem
#define BKH 64
#define ROWB 128
#define STG_BYTES (128 * ROWB)      // 16384
#define STAGE_BYTES (2 * STG_BYTES) // 32768
#define NSTAGE 3
#define GSMEM_BYTES (NSTAGE * STAGE_BYTES)   // 98304 -> 2 CTAs/SM

#define PSLICE 8

// ---------------- device scratch (allocation-free) ----------------
__device__ unsigned long long g_pk[NN];   // packed (count_sd1 << 32) | count_sd0
__device__ float g_dis[NN];
__device__ int   g_cnt[NN];
__device__ int   g_off[NN + 1];
__device__ int   g_bsum[SCAN_NB];
__device__ __align__(16) int2 g_edge[EE]; // interleaved (src, norm-bits)
__device__ __align__(16) __half g_x16[(size_t)NN * DD];
__device__ __align__(16) __half g_wt[(size_t)LL * DD * DD]; // W^T * BNscale fp16 [l][n][k]
__device__ float g_cbias[LL * DD];
__device__ __align__(16) __half g_hw16[(size_t)NN * DD];
__device__ __align__(16) __half g_h16[(size_t)NN * DD];
__device__ int   g_gcnt[BB];
__device__ int   g_gstart[BB + 1];
__device__ float g_psum[PSLICE][BB][DD];
__device__ float g_pmax[PSLICE][BB][DD];
__device__ float g_pool[BB * 2 * DD];

// ---------------- init ----------------
__global__ void init_kernel() {
    int i = blockIdx.x * blockDim.x + threadIdx.x;
    if (i < NN) g_pk[i] = 0ull;
    if (i < BB) g_gcnt[i] = 0;
}

__global__ void edge_deg_kernel(const int* __restrict__ ei,
                                const int* __restrict__ sd) {
    int e = blockIdx.x * blockDim.x + threadIdx.x;
    if (e >= EE) return;
    int col = ei[EE + e];
    unsigned long long inc = (sd[e] == 1) ? (1ull << 32) : 1ull;
    atomicAdd(&g_pk[col], inc);
}

__global__ void finalize_deg_kernel() {
    int i = blockIdx.x * blockDim.x + threadIdx.x;
    if (i >= NN) return;
    unsigned long long pk = g_pk[i];
    unsigned int lo = (unsigned int)(pk & 0xffffffffull);
    unsigned int hi = (unsigned int)(pk >> 32);
    g_cnt[i] = (int)(lo + hi);
    float d = (float)hi + 0.7f * (float)lo + 1.0f;
    g_dis[i] = rsqrtf(fmaxf(d, EPSV));
}

// x -> fp16
__global__ void x2h_kernel(const float* __restrict__ x) {
    size_t i = (size_t)blockIdx.x * blockDim.x + threadIdx.x;
    size_t total = (size_t)NN * DD;
    if (i * 4 < total) {
        float4 v = *(const float4*)(x + i * 4);
        __half2 h0 = __floats2half2_rn(v.x, v.y);
        __half2 h1 = __floats2half2_rn(v.z, v.w);
        *(uint2*)(g_x16 + i * 4) = make_uint2(*(uint32_t*)&h0, *(uint32_t*)&h1);
    }
}

// W[l][k][n] * BNscale[l][n] -> g_wt[l][n][k] fp16
__global__ void wt_kernel(const float* __restrict__ Wc,
                          const float* __restrict__ gamma,
                          const float* __restrict__ rvar) {
    __shared__ float tile[32][33];
    int l = blockIdx.z;
    int n0 = blockIdx.x * 32;
    int k0 = blockIdx.y * 32;
    int tx = threadIdx.x, ty = threadIdx.y;
    tile[ty][tx] = Wc[(size_t)l * DD * DD + (size_t)(k0 + ty) * DD + n0 + tx];
    __syncthreads();
    int n = n0 + ty;
    float scale = gamma[l * DD + n] * rsqrtf(rvar[l * DD + n] + EPSV);
    g_wt[(size_t)l * DD * DD + (size_t)n * DD + k0 + tx] =
        __float2half_rn(tile[tx][ty] * scale);
}

__global__ void cbias_kernel(const float* __restrict__ bc,
                             const float* __restrict__ gamma,
                             const float* __restrict__ beta,
                             const float* __restrict__ rmean,
                             const float* __restrict__ rvar) {
    int i = blockIdx.x * blockDim.x + threadIdx.x;
    if (i >= LL * DD) return;
    float scale = gamma[i] * rsqrtf(rvar[i] + EPSV);
    g_cbias[i] = scale * (bc[i] - rmean[i]) + beta[i];
}

// ---------------- multi-block scan ----------------
__global__ void scan_local_kernel() {
    __shared__ int swarp[8];
    int tid = threadIdx.x;
    int lane = tid & 31, wid = tid >> 5;
    int i = blockIdx.x * SCAN_TPB + tid;
    int v = (i < NN) ? g_cnt[i] : 0;
    int incl = v;
#pragma unroll
    for (int d = 1; d < 32; d <<= 1) {
        int t = __shfl_up_sync(0xffffffff, incl, d);
        if (lane >= d) incl += t;
    }
    if (lane == 31) swarp[wid] = incl;
    __syncthreads();
    if (wid == 0 && lane < 8) {
        int ws = swarp[lane];
        int wincl = ws;
#pragma unroll
        for (int d = 1; d < 8; d <<= 1) {
            int t = __shfl_up_sync(0xff, wincl, d);
            if (lane >= d) wincl += t;
        }
        swarp[lane] = wincl - ws;
        if (lane == 7) g_bsum[blockIdx.x] = wincl;
    }
    __syncthreads();
    if (i < NN) g_off[i] = swarp[wid] + incl - v;
}

__global__ void scan_bsums_kernel() {
    __shared__ int swarp[8];
    int tid = threadIdx.x;
    int lane = tid & 31, wid = tid >> 5;
    int v = (tid < SCAN_NB) ? g_bsum[tid] : 0;
    int incl = v;
#pragma unroll
    for (int d = 1; d < 32; d <<= 1) {
        int t = __shfl_up_sync(0xffffffff, incl, d);
        if (lane >= d) incl += t;
    }
    if (lane == 31) swarp[wid] = incl;
    __syncthreads();
    if (wid == 0 && lane < 8) {
        int ws = swarp[lane];
        int wincl = ws;
#pragma unroll
        for (int d = 1; d < 8; d <<= 1) {
            int t = __shfl_up_sync(0xff, wincl, d);
            if (lane >= d) wincl += t;
        }
        swarp[lane] = wincl - ws;
        if (lane == 7) g_off[NN] = wincl;
    }
    __syncthreads();
    if (tid < SCAN_NB) g_bsum[tid] = swarp[wid] + incl - v;
}

__global__ void scan_add_kernel() {
    int i = blockIdx.x * SCAN_TPB + threadIdx.x;
    if (i < NN) { g_off[i] += g_bsum[blockIdx.x]; g_cnt[i] = 0; }
}

// single 8B scatter per edge
__global__ void bucket_kernel(const int* __restrict__ ei,
                              const int* __restrict__ sd) {
    int e = blockIdx.x * blockDim.x + threadIdx.x;
    if (e >= EE) return;
    int row = ei[e];
    int col = ei[EE + e];
    float w = (sd[e] == 1) ? 1.0f : 0.7f;
    int pos = g_off[col] + atomicAdd(&g_cnt[col], 1);
    float nm = g_dis[row] * w * g_dis[col];
    g_edge[pos] = make_int2(row, __float_as_int(nm));
}

// ============= fp16 mma.sync GEMM, cp.async 3-stage, swizzled =============
__device__ __forceinline__ void mma_f16(float* c, const uint32_t* a, const uint32_t* b) {
    asm volatile(
        "mma.sync.aligned.m16n8k16.row.col.f32.f16.f16.f32 "
        "{%0,%1,%2,%3}, {%4,%5,%6,%7}, {%8,%9}, {%0,%1,%2,%3};\n"
        : "+f"(c[0]), "+f"(c[1]), "+f"(c[2]), "+f"(c[3])
        : "r"(a[0]), "r"(a[1]), "r"(a[2]), "r"(a[3]), "r"(b[0]), "r"(b[1]));
}

__device__ __forceinline__ void ldsm_x4(uint32_t& d0, uint32_t& d1, uint32_t& d2,
                                        uint32_t& d3, uint32_t addr) {
    asm volatile("ldmatrix.sync.aligned.m8n8.x4.shared.b16 {%0,%1,%2,%3}, [%4];"
                 : "=r"(d0), "=r"(d1), "=r"(d2), "=r"(d3) : "r"(addr));
}

__device__ __forceinline__ void cp16(uint32_t dst, const void* src, int srcsize) {
    asm volatile("cp.async.cg.shared.global [%0], [%1], 16, %2;"
                 :: "r"(dst), "l"(src), "r"(srcsize) : "memory");
}

__device__ __forceinline__ uint32_t swz(int row, int ch) {
    return (uint32_t)(row * ROWB + ((ch ^ (row & 7)) << 4));
}

// 256 threads, 8 warps (4M x 2N), warp tile 32x64.
__global__ __launch_bounds__(256)
void gemm_cp_kernel(int use_x, int layer) {
    extern __shared__ char smem[];
    const __half* __restrict__ A = use_x ? g_x16 : g_h16;
    const __half* __restrict__ Bt = g_wt + (size_t)layer * DD * DD;

    int tid = threadIdx.x;
    int lane = tid & 31, warp = tid >> 5;
    int warpM = warp & 3, warpN = warp >> 2;
    int gid = lane >> 2, tig = lane & 3;
    int rowC0 = blockIdx.y * 128;
    int colC0 = blockIdx.x * 128;

    auto load_stage = [&](int kt, int stg) {
        char* sa = smem + stg * STAGE_BYTES;
        char* sb = sa + STG_BYTES;
        uint32_t sa_u = (uint32_t)__cvta_generic_to_shared(sa);
        uint32_t sb_u = (uint32_t)__cvta_generic_to_shared(sb);
#pragma unroll
        for (int i = 0; i < 4; i++) {
            int c = tid + i * 256;
            int row = c >> 3;
            int kc8 = c & 7;
            uint32_t soff = swz(row, kc8);
            int gRow = rowC0 + row;
            const __half* srcA = A + (size_t)gRow * DD + kt * BKH + kc8 * 8;
            cp16(sa_u + soff, srcA, (gRow < NN) ? 16 : 0);
            const __half* srcB = Bt + (size_t)(colC0 + row) * DD + kt * BKH + kc8 * 8;
            cp16(sb_u + soff, srcB, 16);
        }
        asm volatile("cp.async.commit_group;" ::: "memory");
    };

    float acc[2][8][4] = {};

    load_stage(0, 0);
    load_stage(1, 1);

    const int NT = DD / BKH;   // 8
    for (int kt = 0; kt < NT; kt++) {
        if (kt == NT - 1)
            asm volatile("cp.async.wait_group 0;" ::: "memory");
        else
            asm volatile("cp.async.wait_group 1;" ::: "memory");
        __syncthreads();

        if (kt + NSTAGE - 1 < NT)
            load_stage(kt + NSTAGE - 1, (kt + NSTAGE - 1) % NSTAGE);

        int stg = kt % NSTAGE;
        char* sa = smem + stg * STAGE_BYTES;
        char* sb = sa + STG_BYTES;
        uint32_t sa_u = (uint32_t)__cvta_generic_to_shared(sa);
        uint32_t sb_u = (uint32_t)__cvta_generic_to_shared(sb);

#pragma unroll
        for (int ks = 0; ks < BKH / 16; ks++) {
            uint32_t af[2][4];
#pragma unroll
            for (int mt = 0; mt < 2; mt++) {
                int r = warpM * 32 + mt * 16 + (lane & 15);
                int ch = ks * 2 + (lane >> 4);
                ldsm_x4(af[mt][0], af[mt][1], af[mt][2], af[mt][3], sa_u + swz(r, ch));
            }
            uint32_t bf[4][4];
#pragma unroll
            for (int p = 0; p < 4; p++) {
                int n = warpN * 64 + p * 16 + (lane & 7) + ((lane >> 4) * 8);
                int ch = ks * 2 + ((lane >> 3) & 1);
                ldsm_x4(bf[p][0], bf[p][1], bf[p][2], bf[p][3], sb_u + swz(n, ch));
            }
#pragma unroll
            for (int mt = 0; mt < 2; mt++)
#pragma unroll
                for (int nt = 0; nt < 8; nt++)
                    mma_f16(acc[mt][nt], af[mt], &bf[nt >> 1][(nt & 1) * 2]);
        }
    }

    // epilogue: write fp16
#pragma unroll
    for (int mt = 0; mt < 2; mt++) {
        int r0 = rowC0 + warpM * 32 + mt * 16 + gid;
        int r1 = r0 + 8;
#pragma unroll
        for (int nt = 0; nt < 8; nt++) {
            int c = colC0 + warpN * 64 + nt * 8 + tig * 2;
            if (r0 < NN)
                *(__half2*)(g_hw16 + (size_t)r0 * DD + c) =
                    __floats2half2_rn(acc[mt][nt][0], acc[mt][nt][1]);
            if (r1 < NN)
                *(__half2*)(g_hw16 + (size_t)r1 * DD + c) =
                    __floats2half2_rn(acc[mt][nt][2], acc[mt][nt][3]);
        }
    }
}

// ------- aggregation + folded bias + ReLU (2-deep unroll, int2 edges) -------
__global__ __launch_bounds__(64)
void agg_kernel(int layer) {
    int node = blockIdx.x;
    int t = threadIdx.x;               // channels [8t, 8t+7]
    const uint4* hw = (const uint4*)g_hw16;
    int s = g_off[node], e = g_off[node + 1];

    float dn = g_dis[node];
    float sn = dn * dn;

    float acc[8];
    {
        uint4 v = hw[(size_t)node * 64 + t];
        float2 f0 = __half22float2(*(const __half2*)&v.x);
        float2 f1 = __half22float2(*(const __half2*)&v.y);
        float2 f2 = __half22float2(*(const __half2*)&v.z);
        float2 f3 = __half22float2(*(const __half2*)&v.w);
        acc[0] = sn * f0.x; acc[1] = sn * f0.y; acc[2] = sn * f1.x; acc[3] = sn * f1.y;
        acc[4] = sn * f2.x; acc[5] = sn * f2.y; acc[6] = sn * f3.x; acc[7] = sn * f3.y;
    }

    int j = s;
    for (; j + 2 <= e; j += 2) {
        int2 e0 = g_edge[j], e1 = g_edge[j + 1];
        float n0 = __int_as_float(e0.y), n1 = __int_as_float(e1.y);
        uint4 v0 = hw[(size_t)e0.x * 64 + t];
        uint4 v1 = hw[(size_t)e1.x * 64 + t];
        float2 a0 = __half22float2(*(const __half2*)&v0.x);
        float2 a1 = __half22float2(*(const __half2*)&v0.y);
        float2 a2 = __half22float2(*(const __half2*)&v0.z);
        float2 a3 = __half22float2(*(const __half2*)&v0.w);
        float2 b0 = __half22float2(*(const __half2*)&v1.x);
        float2 b1 = __half22float2(*(const __half2*)&v1.y);
        float2 b2 = __half22float2(*(const __half2*)&v1.z);
        float2 b3 = __half22float2(*(const __half2*)&v1.w);
        acc[0] += n0 * a0.x + n1 * b0.x;
        acc[1] += n0 * a0.y + n1 * b0.y;
        acc[2] += n0 * a1.x + n1 * b1.x;
        acc[3] += n0 * a1.y + n1 * b1.y;
        acc[4] += n0 * a2.x + n1 * b2.x;
        acc[5] += n0 * a2.y + n1 * b2.y;
        acc[6] += n0 * a3.x + n1 * b3.x;
        acc[7] += n0 * a3.y + n1 * b3.y;
    }
    if (j < e) {
        int2 ed = g_edge[j];
        float nw = __int_as_float(ed.y);
        uint4 v = hw[(size_t)ed.x * 64 + t];
        float2 f0 = __half22float2(*(const __half2*)&v.x);
        float2 f1 = __half22float2(*(const __half2*)&v.y);
        float2 f2 = __half22float2(*(const __half2*)&v.z);
        float2 f3 = __half22float2(*(const __half2*)&v.w);
        acc[0] += nw * f0.x; acc[1] += nw * f0.y; acc[2] += nw * f1.x; acc[3] += nw * f1.y;
        acc[4] += nw * f2.x; acc[5] += nw * f2.y; acc[6] += nw * f3.x; acc[7] += nw * f3.y;
    }

    float4 cb0 = ((const float4*)g_cbias)[layer * 128 + 2 * t];
    float4 cb1 = ((const float4*)g_cbias)[layer * 128 + 2 * t + 1];
    float o0 = fmaxf(acc[0] + cb0.x, 0.f);
    float o1 = fmaxf(acc[1] + cb0.y, 0.f);
    float o2 = fmaxf(acc[2] + cb0.z, 0.f);
    float o3 = fmaxf(acc[3] + cb0.w, 0.f);
    float o4 = fmaxf(acc[4] + cb1.x, 0.f);
    float o5 = fmaxf(acc[5] + cb1.y, 0.f);
    float o6 = fmaxf(acc[6] + cb1.z, 0.f);
    float o7 = fmaxf(acc[7] + cb1.w, 0.f);
    __half2 h0 = __floats2half2_rn(o0, o1);
    __half2 h1 = __floats2half2_rn(o2, o3);
    __half2 h2 = __floats2half2_rn(o4, o5);
    __half2 h3 = __floats2half2_rn(o6, o7);
    ((uint4*)g_h16)[(size_t)node * 64 + t] =
        make_uint4(*(uint32_t*)&h0, *(uint32_t*)&h1, *(uint32_t*)&h2, *(uint32_t*)&h3);
}

// ---------------- pooling (sliced) ----------------
__global__ void batch_count_kernel(const int* __restrict__ batch) {
    int i = blockIdx.x * blockDim.x + threadIdx.x;
    if (i < NN) atomicAdd(&g_gcnt[batch[i]], 1);
}

__global__ void gscan_kernel() {
    if (threadIdx.x == 0) {
        int run = 0;
        for (int b = 0; b < BB; b++) { g_gstart[b] = run; run += g_gcnt[b]; }
        g_gstart[BB] = run;
    }
}

__global__ void pool_part_kernel() {
    int b = blockIdx.x;
    int c = blockIdx.y * 128 + threadIdx.x;
    int si = blockIdx.z;
    int gs = g_gstart[b], ge = g_gstart[b + 1];
    int len = ge - gs;
    int s = gs + (int)((long long)len * si / PSLICE);
    int e = gs + (int)((long long)len * (si + 1) / PSLICE);
    float sum0 = 0.f, sum1 = 0.f, sum2 = 0.f, sum3 = 0.f;
    float mx0 = -3.0e38f, mx1 = -3.0e38f, mx2 = -3.0e38f, mx3 = -3.0e38f;
    int n = s;
    for (; n + 4 <= e; n += 4) {
        float v0 = __half2float(g_h16[(size_t)n * DD + c]);
        float v1 = __half2float(g_h16[(size_t)(n + 1) * DD + c]);
        float v2 = __half2float(g_h16[(size_t)(n + 2) * DD + c]);
        float v3 = __half2float(g_h16[(size_t)(n + 3) * DD + c]);
        sum0 += v0; sum1 += v1; sum2 += v2; sum3 += v3;
        mx0 = fmaxf(mx0, v0); mx1 = fmaxf(mx1, v1);
        mx2 = fmaxf(mx2, v2); mx3 = fmaxf(mx3, v3);
    }
    for (; n < e; n++) {
        float v = __half2float(g_h16[(size_t)n * DD + c]);
        sum0 += v; mx0 = fmaxf(mx0, v);
    }
    g_psum[si][b][c] = (sum0 + sum1) + (sum2 + sum3);
    g_pmax[si][b][c] = fmaxf(fmaxf(mx0, mx1), fmaxf(mx2, mx3));
}

__global__ void pool_combine_kernel() {
    int b = blockIdx.x;
    int c = blockIdx.y * 128 + threadIdx.x;
    float sum = 0.f, mx = -3.0e38f;
#pragma unroll
    for (int si = 0; si < PSLICE; si++) {
        sum += g_psum[si][b][c];
        mx = fmaxf(mx, g_pmax[si][b][c]);
    }
    int cnt = g_gstart[b + 1] - g_gstart[b];
    float mean = sum / fmaxf((float)cnt, 1.0f);
    if (cnt == 0) mx = 0.f;
    g_pool[b * 2 * DD + c] = mean;
    g_pool[b * 2 * DD + DD + c] = mx;
}

// ---------------- head ----------------
__global__ void final_kernel(const float* __restrict__ Wlin,
                             const float* __restrict__ blin,
                             float* __restrict__ out) {
    int b = blockIdx.x;
    int tid = threadIdx.x;
    const float* p = g_pool + b * 2 * DD;
    float a0 = 0.f, a1 = 0.f;
    for (int j = tid; j < 2 * DD; j += 256) {
        float v = p[j];
        a0 += v * Wlin[2 * j];
        a1 += v * Wlin[2 * j + 1];
    }
    __shared__ float s0[256], s1[256];
    s0[tid] = a0; s1[tid] = a1;
    __syncthreads();
    for (int off = 128; off > 0; off >>= 1) {
        if (tid < off) { s0[tid] += s0[tid + off]; s1[tid] += s1[tid + off]; }
        __syncthreads();
    }
    if (tid == 0) {
        float z0 = s0[0] + blin[0];
        float z1 = s1[0] + blin[1];
        float m = fmaxf(z0, z1);
        float ls = logf(expf(z0 - m) + expf(z1 - m));
        out[b * 2 + 0] = z0 - m - ls;
        out[b * 2 + 1] = z1 - m - ls;
    }
}

// ---------------- launch ----------------
extern "C" void kernel_launch(void* const* d_in, const int* in_sizes, int n_in,
                              void* d_out, int out_size) {
    const float* x     = (const float*)d_in[0];
    const int*   ei    = (const int*)d_in[1];
    const int*   batch = (const int*)d_in[2];
    const int*   sd    = (const int*)d_in[3];
    const float* Wc    = (const float*)d_in[4];
    const float* bc    = (const float*)d_in[5];
    const float* gamma = (const float*)d_in[6];
    const float* beta  = (const float*)d_in[7];
    const float* rmean = (const float*)d_in[8];
    const float* rvar  = (const float*)d_in[9];
    const float* Wlin  = (const float*)d_in[10];
    const float* blin  = (const float*)d_in[11];
    float* out = (float*)d_out;

    cudaFuncSetAttribute(gemm_cp_kernel,
                         cudaFuncAttributeMaxDynamicSharedMemorySize, GSMEM_BYTES);

    const int TPB = 256;
    int gN = (NN + TPB - 1) / TPB;
    int gE = (EE + TPB - 1) / TPB;
    dim3 ggrid(DD / 128, (NN + 127) / 128);

    x2h_kernel<<<(NN * DD / 4 + TPB - 1) / TPB, TPB>>>(x);
    wt_kernel<<<dim3(16, 16, LL), dim3(32, 32)>>>(Wc, gamma, rvar);
    init_kernel<<<gN, TPB>>>();
    gemm_cp_kernel<<<ggrid, 256, GSMEM_BYTES>>>(1, 0);      // 4th launch -> profiled

    edge_deg_kernel<<<gE, TPB>>>(ei, sd);
    finalize_deg_kernel<<<gN, TPB>>>();
    scan_local_kernel<<<SCAN_NB, SCAN_TPB>>>();
    scan_bsums_kernel<<<1, SCAN_TPB>>>();
    scan_add_kernel<<<SCAN_NB, SCAN_TPB>>>();
    bucket_kernel<<<gE, TPB>>>(ei, sd);
    batch_count_kernel<<<gN, TPB>>>(batch);
    gscan_kernel<<<1, 32>>>();
    cbias_kernel<<<(LL * DD + TPB - 1) / TPB, TPB>>>(bc, gamma, beta, rmean, rvar);

    agg_kernel<<<NN, 64>>>(0);
    for (int l = 1; l < LL; l++) {
        gemm_cp_kernel<<<ggrid, 256, GSMEM_BYTES>>>(0, l);
        agg_kernel<<<NN, 64>>>(l);
    }

    pool_part_kernel<<<dim3(BB, DD / 128, PSLICE), 128>>>();
    pool_combine_kernel<<<dim3(BB, DD / 128), 128>>>();
    final_kernel<<<BB, 256>>>(Wlin, blin, out);
}

// round 16
// speedup vs baseline: 1.4465x; 1.0166x over previous
#include <cuda_runtime.h>
#include <cuda_fp16.h>
#include <math.h>
#include <stdint.h>

// Problem constants
#define NN 50000
#define EE 800000
#define DD 512
#define BB 64
#define LL 4
#define EPSV 1e-5f

#define SCAN_TPB 256
#define SCAN_NB ((NN + SCAN_TPB - 1) / SCAN_TPB)   // 196

// GEMM config: BM=BN=128, BK=64 halves, 3-stage cp.async, XOR-swizzled smem
#define BKH 64
#define ROWB 128
#define STG_BYTES (128 * ROWB)      // 16384
#define STAGE_BYTES (2 * STG_BYTES) // 32768
#define NSTAGE 3
#define GSMEM_BYTES (NSTAGE * STAGE_BYTES)   // 98304 -> 2 CTAs/SM

#define PSLICE 8

// ---------------- device scratch (allocation-free) ----------------
__device__ unsigned long long g_pk[NN];   // packed (count_sd1 << 32) | count_sd0
__device__ float g_dis[NN];
__device__ int   g_cnt[NN];
__device__ int   g_off[NN + 1];
__device__ int   g_bsum[SCAN_NB];
__device__ __align__(16) int2 g_edge[EE]; // interleaved (src, norm-bits)
__device__ __align__(16) __half g_x16[(size_t)NN * DD];
__device__ __align__(16) __half g_wt[(size_t)LL * DD * DD]; // W^T * BNscale fp16 [l][n][k]
__device__ float g_cbias[LL * DD];
__device__ __align__(16) __half g_hw16[(size_t)NN * DD];
__device__ __align__(16) __half g_h16[(size_t)NN * DD];
__device__ int   g_gcnt[BB];
__device__ int   g_gstart[BB + 1];
__device__ float g_psum[PSLICE][BB][DD];
__device__ float g_pmax[PSLICE][BB][DD];
__device__ float g_pool[BB * 2 * DD];

// ---------------- init ----------------
__global__ void init_kernel() {
    int i = blockIdx.x * blockDim.x + threadIdx.x;
    if (i < NN) g_pk[i] = 0ull;
    if (i < BB) g_gcnt[i] = 0;
}

__global__ void edge_deg_kernel(const int* __restrict__ ei,
                                const int* __restrict__ sd) {
    int e = blockIdx.x * blockDim.x + threadIdx.x;
    if (e >= EE) return;
    int col = ei[EE + e];
    unsigned long long inc = (sd[e] == 1) ? (1ull << 32) : 1ull;
    atomicAdd(&g_pk[col], inc);
}

__global__ void finalize_deg_kernel() {
    int i = blockIdx.x * blockDim.x + threadIdx.x;
    if (i >= NN) return;
    unsigned long long pk = g_pk[i];
    unsigned int lo = (unsigned int)(pk & 0xffffffffull);
    unsigned int hi = (unsigned int)(pk >> 32);
    g_cnt[i] = (int)(lo + hi);
    float d = (float)hi + 0.7f * (float)lo + 1.0f;
    g_dis[i] = rsqrtf(fmaxf(d, EPSV));
}

// x -> fp16
__global__ void x2h_kernel(const float* __restrict__ x) {
    size_t i = (size_t)blockIdx.x * blockDim.x + threadIdx.x;
    size_t total = (size_t)NN * DD;
    if (i * 4 < total) {
        float4 v = *(const float4*)(x + i * 4);
        __half2 h0 = __floats2half2_rn(v.x, v.y);
        __half2 h1 = __floats2half2_rn(v.z, v.w);
        *(uint2*)(g_x16 + i * 4) = make_uint2(*(uint32_t*)&h0, *(uint32_t*)&h1);
    }
}

// W[l][k][n] * BNscale[l][n] -> g_wt[l][n][k] fp16
__global__ void wt_kernel(const float* __restrict__ Wc,
                          const float* __restrict__ gamma,
                          const float* __restrict__ rvar) {
    __shared__ float tile[32][33];
    int l = blockIdx.z;
    int n0 = blockIdx.x * 32;
    int k0 = blockIdx.y * 32;
    int tx = threadIdx.x, ty = threadIdx.y;
    tile[ty][tx] = Wc[(size_t)l * DD * DD + (size_t)(k0 + ty) * DD + n0 + tx];
    __syncthreads();
    int n = n0 + ty;
    float scale = gamma[l * DD + n] * rsqrtf(rvar[l * DD + n] + EPSV);
    g_wt[(size_t)l * DD * DD + (size_t)n * DD + k0 + tx] =
        __float2half_rn(tile[tx][ty] * scale);
}

__global__ void cbias_kernel(const float* __restrict__ bc,
                             const float* __restrict__ gamma,
                             const float* __restrict__ beta,
                             const float* __restrict__ rmean,
                             const float* __restrict__ rvar) {
    int i = blockIdx.x * blockDim.x + threadIdx.x;
    if (i >= LL * DD) return;
    float scale = gamma[i] * rsqrtf(rvar[i] + EPSV);
    g_cbias[i] = scale * (bc[i] - rmean[i]) + beta[i];
}

// ---------------- multi-block scan ----------------
__global__ void scan_local_kernel() {
    __shared__ int swarp[8];
    int tid = threadIdx.x;
    int lane = tid & 31, wid = tid >> 5;
    int i = blockIdx.x * SCAN_TPB + tid;
    int v = (i < NN) ? g_cnt[i] : 0;
    int incl = v;
#pragma unroll
    for (int d = 1; d < 32; d <<= 1) {
        int t = __shfl_up_sync(0xffffffff, incl, d);
        if (lane >= d) incl += t;
    }
    if (lane == 31) swarp[wid] = incl;
    __syncthreads();
    if (wid == 0 && lane < 8) {
        int ws = swarp[lane];
        int wincl = ws;
#pragma unroll
        for (int d = 1; d < 8; d <<= 1) {
            int t = __shfl_up_sync(0xff, wincl, d);
            if (lane >= d) wincl += t;
        }
        swarp[lane] = wincl - ws;
        if (lane == 7) g_bsum[blockIdx.x] = wincl;
    }
    __syncthreads();
    if (i < NN) g_off[i] = swarp[wid] + incl - v;
}

__global__ void scan_bsums_kernel() {
    __shared__ int swarp[8];
    int tid = threadIdx.x;
    int lane = tid & 31, wid = tid >> 5;
    int v = (tid < SCAN_NB) ? g_bsum[tid] : 0;
    int incl = v;
#pragma unroll
    for (int d = 1; d < 32; d <<= 1) {
        int t = __shfl_up_sync(0xffffffff, incl, d);
        if (lane >= d) incl += t;
    }
    if (lane == 31) swarp[wid] = incl;
    __syncthreads();
    if (wid == 0 && lane < 8) {
        int ws = swarp[lane];
        int wincl = ws;
#pragma unroll
        for (int d = 1; d < 8; d <<= 1) {
            int t = __shfl_up_sync(0xff, wincl, d);
            if (lane >= d) wincl += t;
        }
        swarp[lane] = wincl - ws;
        if (lane == 7) g_off[NN] = wincl;
    }
    __syncthreads();
    if (tid < SCAN_NB) g_bsum[tid] = swarp[wid] + incl - v;
}

__global__ void scan_add_kernel() {
    int i = blockIdx.x * SCAN_TPB + threadIdx.x;
    if (i < NN) { g_off[i] += g_bsum[blockIdx.x]; g_cnt[i] = 0; }
}

// single 8B scatter per edge
__global__ void bucket_kernel(const int* __restrict__ ei,
                              const int* __restrict__ sd) {
    int e = blockIdx.x * blockDim.x + threadIdx.x;
    if (e >= EE) return;
    int row = ei[e];
    int col = ei[EE + e];
    float w = (sd[e] == 1) ? 1.0f : 0.7f;
    int pos = g_off[col] + atomicAdd(&g_cnt[col], 1);
    float nm = g_dis[row] * w * g_dis[col];
    g_edge[pos] = make_int2(row, __float_as_int(nm));
}

// ============= fp16 mma.sync GEMM, cp.async 3-stage, swizzled =============
__device__ __forceinline__ void mma_f16(float* c, const uint32_t* a, const uint32_t* b) {
    asm volatile(
        "mma.sync.aligned.m16n8k16.row.col.f32.f16.f16.f32 "
        "{%0,%1,%2,%3}, {%4,%5,%6,%7}, {%8,%9}, {%0,%1,%2,%3};\n"
        : "+f"(c[0]), "+f"(c[1]), "+f"(c[2]), "+f"(c[3])
        : "r"(a[0]), "r"(a[1]), "r"(a[2]), "r"(a[3]), "r"(b[0]), "r"(b[1]));
}

__device__ __forceinline__ void ldsm_x4(uint32_t& d0, uint32_t& d1, uint32_t& d2,
                                        uint32_t& d3, uint32_t addr) {
    asm volatile("ldmatrix.sync.aligned.m8n8.x4.shared.b16 {%0,%1,%2,%3}, [%4];"
                 : "=r"(d0), "=r"(d1), "=r"(d2), "=r"(d3) : "r"(addr));
}

__device__ __forceinline__ void cp16(uint32_t dst, const void* src, int srcsize) {
    asm volatile("cp.async.cg.shared.global [%0], [%1], 16, %2;"
                 :: "r"(dst), "l"(src), "r"(srcsize) : "memory");
}

__device__ __forceinline__ uint32_t swz(int row, int ch) {
    return (uint32_t)(row * ROWB + ((ch ^ (row & 7)) << 4));
}

// 256 threads, 8 warps (4M x 2N), warp tile 32x64.
__global__ __launch_bounds__(256)
void gemm_cp_kernel(int use_x, int layer) {
    extern __shared__ char smem[];
    const __half* __restrict__ A = use_x ? g_x16 : g_h16;
    const __half* __restrict__ Bt = g_wt + (size_t)layer * DD * DD;

    int tid = threadIdx.x;
    int lane = tid & 31, warp = tid >> 5;
    int warpM = warp & 3, warpN = warp >> 2;
    int gid = lane >> 2, tig = lane & 3;
    int rowC0 = blockIdx.y * 128;
    int colC0 = blockIdx.x * 128;

    auto load_stage = [&](int kt, int stg) {
        char* sa = smem + stg * STAGE_BYTES;
        char* sb = sa + STG_BYTES;
        uint32_t sa_u = (uint32_t)__cvta_generic_to_shared(sa);
        uint32_t sb_u = (uint32_t)__cvta_generic_to_shared(sb);
#pragma unroll
        for (int i = 0; i < 4; i++) {
            int c = tid + i * 256;
            int row = c >> 3;
            int kc8 = c & 7;
            uint32_t soff = swz(row, kc8);
            int gRow = rowC0 + row;
            const __half* srcA = A + (size_t)gRow * DD + kt * BKH + kc8 * 8;
            cp16(sa_u + soff, srcA, (gRow < NN) ? 16 : 0);
            const __half* srcB = Bt + (size_t)(colC0 + row) * DD + kt * BKH + kc8 * 8;
            cp16(sb_u + soff, srcB, 16);
        }
        asm volatile("cp.async.commit_group;" ::: "memory");
    };

    float acc[2][8][4] = {};

    load_stage(0, 0);
    load_stage(1, 1);

    const int NT = DD / BKH;   // 8
    for (int kt = 0; kt < NT; kt++) {
        if (kt == NT - 1)
            asm volatile("cp.async.wait_group 0;" ::: "memory");
        else
            asm volatile("cp.async.wait_group 1;" ::: "memory");
        __syncthreads();

        if (kt + NSTAGE - 1 < NT)
            load_stage(kt + NSTAGE - 1, (kt + NSTAGE - 1) % NSTAGE);

        int stg = kt % NSTAGE;
        char* sa = smem + stg * STAGE_BYTES;
        char* sb = sa + STG_BYTES;
        uint32_t sa_u = (uint32_t)__cvta_generic_to_shared(sa);
        uint32_t sb_u = (uint32_t)__cvta_generic_to_shared(sb);

#pragma unroll
        for (int ks = 0; ks < BKH / 16; ks++) {
            uint32_t af[2][4];
#pragma unroll
            for (int mt = 0; mt < 2; mt++) {
                int r = warpM * 32 + mt * 16 + (lane & 15);
                int ch = ks * 2 + (lane >> 4);
                ldsm_x4(af[mt][0], af[mt][1], af[mt][2], af[mt][3], sa_u + swz(r, ch));
            }
            uint32_t bf[4][4];
#pragma unroll
            for (int p = 0; p < 4; p++) {
                int n = warpN * 64 + p * 16 + (lane & 7) + ((lane >> 4) * 8);
                int ch = ks * 2 + ((lane >> 3) & 1);
                ldsm_x4(bf[p][0], bf[p][1], bf[p][2], bf[p][3], sb_u + swz(n, ch));
            }
#pragma unroll
            for (int mt = 0; mt < 2; mt++)
#pragma unroll
                for (int nt = 0; nt < 8; nt++)
                    mma_f16(acc[mt][nt], af[mt], &bf[nt >> 1][(nt & 1) * 2]);
        }
    }

    // epilogue: write fp16
#pragma unroll
    for (int mt = 0; mt < 2; mt++) {
        int r0 = rowC0 + warpM * 32 + mt * 16 + gid;
        int r1 = r0 + 8;
#pragma unroll
        for (int nt = 0; nt < 8; nt++) {
            int c = colC0 + warpN * 64 + nt * 8 + tig * 2;
            if (r0 < NN)
                *(__half2*)(g_hw16 + (size_t)r0 * DD + c) =
                    __floats2half2_rn(acc[mt][nt][0], acc[mt][nt][1]);
            if (r1 < NN)
                *(__half2*)(g_hw16 + (size_t)r1 * DD + c) =
                    __floats2half2_rn(acc[mt][nt][2], acc[mt][nt][3]);
        }
    }
}

// ------- aggregation + folded bias + ReLU (2-deep unroll, int2 edges) -------
__global__ __launch_bounds__(64)
void agg_kernel(int layer) {
    int node = blockIdx.x;
    int t = threadIdx.x;               // channels [8t, 8t+7]
    const uint4* hw = (const uint4*)g_hw16;
    int s = g_off[node], e = g_off[node + 1];

    float dn = g_dis[node];
    float sn = dn * dn;

    float acc[8];
    {
        uint4 v = hw[(size_t)node * 64 + t];
        float2 f0 = __half22float2(*(const __half2*)&v.x);
        float2 f1 = __half22float2(*(const __half2*)&v.y);
        float2 f2 = __half22float2(*(const __half2*)&v.z);
        float2 f3 = __half22float2(*(const __half2*)&v.w);
        acc[0] = sn * f0.x; acc[1] = sn * f0.y; acc[2] = sn * f1.x; acc[3] = sn * f1.y;
        acc[4] = sn * f2.x; acc[5] = sn * f2.y; acc[6] = sn * f3.x; acc[7] = sn * f3.y;
    }

    int j = s;
    for (; j + 2 <= e; j += 2) {
        int2 e0 = g_edge[j], e1 = g_edge[j + 1];
        float n0 = __int_as_float(e0.y), n1 = __int_as_float(e1.y);
        uint4 v0 = hw[(size_t)e0.x * 64 + t];
        uint4 v1 = hw[(size_t)e1.x * 64 + t];
        float2 a0 = __half22float2(*(const __half2*)&v0.x);
        float2 a1 = __half22float2(*(const __half2*)&v0.y);
        float2 a2 = __half22float2(*(const __half2*)&v0.z);
        float2 a3 = __half22float2(*(const __half2*)&v0.w);
        float2 b0 = __half22float2(*(const __half2*)&v1.x);
        float2 b1 = __half22float2(*(const __half2*)&v1.y);
        float2 b2 = __half22float2(*(const __half2*)&v1.z);
        float2 b3 = __half22float2(*(const __half2*)&v1.w);
        acc[0] += n0 * a0.x + n1 * b0.x;
        acc[1] += n0 * a0.y + n1 * b0.y;
        acc[2] += n0 * a1.x + n1 * b1.x;
        acc[3] += n0 * a1.y + n1 * b1.y;
        acc[4] += n0 * a2.x + n1 * b2.x;
        acc[5] += n0 * a2.y + n1 * b2.y;
        acc[6] += n0 * a3.x + n1 * b3.x;
        acc[7] += n0 * a3.y + n1 * b3.y;
    }
    if (j < e) {
        int2 ed = g_edge[j];
        float nw = __int_as_float(ed.y);
        uint4 v = hw[(size_t)ed.x * 64 + t];
        float2 f0 = __half22float2(*(const __half2*)&v.x);
        float2 f1 = __half22float2(*(const __half2*)&v.y);
        float2 f2 = __half22float2(*(const __half2*)&v.z);
        float2 f3 = __half22float2(*(const __half2*)&v.w);
        acc[0] += nw * f0.x; acc[1] += nw * f0.y; acc[2] += nw * f1.x; acc[3] += nw * f1.y;
        acc[4] += nw * f2.x; acc[5] += nw * f2.y; acc[6] += nw * f3.x; acc[7] += nw * f3.y;
    }

    float4 cb0 = ((const float4*)g_cbias)[layer * 128 + 2 * t];
    float4 cb1 = ((const float4*)g_cbias)[layer * 128 + 2 * t + 1];
    float o0 = fmaxf(acc[0] + cb0.x, 0.f);
    float o1 = fmaxf(acc[1] + cb0.y, 0.f);
    float o2 = fmaxf(acc[2] + cb0.z, 0.f);
    float o3 = fmaxf(acc[3] + cb0.w, 0.f);
    float o4 = fmaxf(acc[4] + cb1.x, 0.f);
    float o5 = fmaxf(acc[5] + cb1.y, 0.f);
    float o6 = fmaxf(acc[6] + cb1.z, 0.f);
    float o7 = fmaxf(acc[7] + cb1.w, 0.f);
    __half2 h0 = __floats2half2_rn(o0, o1);
    __half2 h1 = __floats2half2_rn(o2, o3);
    __half2 h2 = __floats2half2_rn(o4, o5);
    __half2 h3 = __floats2half2_rn(o6, o7);
    ((uint4*)g_h16)[(size_t)node * 64 + t] =
        make_uint4(*(uint32_t*)&h0, *(uint32_t*)&h1, *(uint32_t*)&h2, *(uint32_t*)&h3);
}

// ---------------- pooling (sliced) ----------------
__global__ void batch_count_kernel(const int* __restrict__ batch) {
    int i = blockIdx.x * blockDim.x + threadIdx.x;
    if (i < NN) atomicAdd(&g_gcnt[batch[i]], 1);
}

__global__ void gscan_kernel() {
    if (threadIdx.x == 0) {
        int run = 0;
        for (int b = 0; b < BB; b++) { g_gstart[b] = run; run += g_gcnt[b]; }
        g_gstart[BB] = run;
    }
}

__global__ void pool_part_kernel() {
    int b = blockIdx.x;
    int c = blockIdx.y * 128 + threadIdx.x;
    int si = blockIdx.z;
    int gs = g_gstart[b], ge = g_gstart[b + 1];
    int len = ge - gs;
    int s = gs + (int)((long long)len * si / PSLICE);
    int e = gs + (int)((long long)len * (si + 1) / PSLICE);
    float sum0 = 0.f, sum1 = 0.f, sum2 = 0.f, sum3 = 0.f;
    float mx0 = -3.0e38f, mx1 = -3.0e38f, mx2 = -3.0e38f, mx3 = -3.0e38f;
    int n = s;
    for (; n + 4 <= e; n += 4) {
        float v0 = __half2float(g_h16[(size_t)n * DD + c]);
        float v1 = __half2float(g_h16[(size_t)(n + 1) * DD + c]);
        float v2 = __half2float(g_h16[(size_t)(n + 2) * DD + c]);
        float v3 = __half2float(g_h16[(size_t)(n + 3) * DD + c]);
        sum0 += v0; sum1 += v1; sum2 += v2; sum3 += v3;
        mx0 = fmaxf(mx0, v0); mx1 = fmaxf(mx1, v1);
        mx2 = fmaxf(mx2, v2); mx3 = fmaxf(mx3, v3);
    }
    for (; n < e; n++) {
        float v = __half2float(g_h16[(size_t)n * DD + c]);
        sum0 += v; mx0 = fmaxf(mx0, v);
    }
    g_psum[si][b][c] = (sum0 + sum1) + (sum2 + sum3);
    g_pmax[si][b][c] = fmaxf(fmaxf(mx0, mx1), fmaxf(mx2, mx3));
}

__global__ void pool_combine_kernel() {
    int b = blockIdx.x;
    int c = blockIdx.y * 128 + threadIdx.x;
    float sum = 0.f, mx = -3.0e38f;
#pragma unroll
    for (int si = 0; si < PSLICE; si++) {
        sum += g_psum[si][b][c];
        mx = fmaxf(mx, g_pmax[si][b][c]);
    }
    int cnt = g_gstart[b + 1] - g_gstart[b];
    float mean = sum / fmaxf((float)cnt, 1.0f);
    if (cnt == 0) mx = 0.f;
    g_pool[b * 2 * DD + c] = mean;
    g_pool[b * 2 * DD + DD + c] = mx;
}

// ---------------- head ----------------
__global__ void final_kernel(const float* __restrict__ Wlin,
                             const float* __restrict__ blin,
                             float* __restrict__ out) {
    int b = blockIdx.x;
    int tid = threadIdx.x;
    const float* p = g_pool + b * 2 * DD;
    float a0 = 0.f, a1 = 0.f;
    for (int j = tid; j < 2 * DD; j += 256) {
        float v = p[j];
        a0 += v * Wlin[2 * j];
        a1 += v * Wlin[2 * j + 1];
    }
    __shared__ float s0[256], s1[256];
    s0[tid] = a0; s1[tid] = a1;
    __syncthreads();
    for (int off = 128; off > 0; off >>= 1) {
        if (tid < off) { s0[tid] += s0[tid + off]; s1[tid] += s1[tid + off]; }
        __syncthreads();
    }
    if (tid == 0) {
        float z0 = s0[0] + blin[0];
        float z1 = s1[0] + blin[1];
        float m = fmaxf(z0, z1);
        float ls = logf(expf(z0 - m) + expf(z1 - m));
        out[b * 2 + 0] = z0 - m - ls;
        out[b * 2 + 1] = z1 - m - ls;
    }
}

// ---------------- launch (dual-stream prologue overlap) ----------------
extern "C" void kernel_launch(void* const* d_in, const int* in_sizes, int n_in,
                              void* d_out, int out_size) {
    const float* x     = (const float*)d_in[0];
    const int*   ei    = (const int*)d_in[1];
    const int*   batch = (const int*)d_in[2];
    const int*   sd    = (const int*)d_in[3];
    const float* Wc    = (const float*)d_in[4];
    const float* bc    = (const float*)d_in[5];
    const float* gamma = (const float*)d_in[6];
    const float* beta  = (const float*)d_in[7];
    const float* rmean = (const float*)d_in[8];
    const float* rvar  = (const float*)d_in[9];
    const float* Wlin  = (const float*)d_in[10];
    const float* blin  = (const float*)d_in[11];
    float* out = (float*)d_out;

    cudaFuncSetAttribute(gemm_cp_kernel,
                         cudaFuncAttributeMaxDynamicSharedMemorySize, GSMEM_BYTES);

    const int TPB = 256;
    int gN = (NN + TPB - 1) / TPB;
    int gE = (EE + TPB - 1) / TPB;
    dim3 ggrid(DD / 128, (NN + 127) / 128);

    // Fork a side stream for the CSR/pool prologue; it is independent of
    // x2h/wt/gemm0. kernel_launch runs only twice (correctness + capture),
    // so per-call stream/event creation is negligible; graph replays reuse
    // the captured parallel structure. Forked work is joined back to the
    // main stream before agg layer 0 (which needs both).
    cudaStream_t s2;
    cudaStreamCreate(&s2);
    cudaEvent_t evFork, evJoin;
    cudaEventCreateWithFlags(&evFork, cudaEventDisableTiming);
    cudaEventCreateWithFlags(&evJoin, cudaEventDisableTiming);

    cudaEventRecord(evFork, 0);
    cudaStreamWaitEvent(s2, evFork, 0);

    // side stream: CSR build + pooling metadata + folded bias
    init_kernel<<<gN, TPB, 0, s2>>>();
    edge_deg_kernel<<<gE, TPB, 0, s2>>>(ei, sd);
    finalize_deg_kernel<<<gN, TPB, 0, s2>>>();
    scan_local_kernel<<<SCAN_NB, SCAN_TPB, 0, s2>>>();
    scan_bsums_kernel<<<1, SCAN_TPB, 0, s2>>>();
    scan_add_kernel<<<SCAN_NB, SCAN_TPB, 0, s2>>>();
    bucket_kernel<<<gE, TPB, 0, s2>>>(ei, sd);
    batch_count_kernel<<<gN, TPB, 0, s2>>>(batch);
    gscan_kernel<<<1, 32, 0, s2>>>();
    cbias_kernel<<<(LL * DD + TPB - 1) / TPB, TPB, 0, s2>>>(bc, gamma, beta, rmean, rvar);
    cudaEventRecord(evJoin, s2);

    // main stream: fp16 conversion + weight prep + GEMM layer 0
    x2h_kernel<<<(NN * DD / 4 + TPB - 1) / TPB, TPB>>>(x);
    wt_kernel<<<dim3(16, 16, LL), dim3(32, 32)>>>(Wc, gamma, rvar);
    gemm_cp_kernel<<<ggrid, 256, GSMEM_BYTES>>>(1, 0);

    // join: agg0 needs CSR + cbias + gemm0 output
    cudaStreamWaitEvent(0, evJoin, 0);

    agg_kernel<<<NN, 64>>>(0);
    for (int l = 1; l < LL; l++) {
        gemm_cp_kernel<<<ggrid, 256, GSMEM_BYTES>>>(0, l);
        agg_kernel<<<NN, 64>>>(l);
    }

    pool_part_kernel<<<dim3(BB, DD / 128, PSLICE), 128>>>();
    pool_combine_kernel<<<dim3(BB, DD / 128), 128>>>();
    final_kernel<<<BB, 256>>>(Wlin, blin, out);
}